// round 1
// baseline (speedup 1.0000x reference)
#include <cuda_runtime.h>
#include <cstdint>
#include <cstddef>

#define LN_EPS 1e-5f

// Problem constants: B=1, N=128, L=256, P=32, K=P*P=1024, n_out=128, M=L*P=8192
// pair matrix: [8192 x 8192] fp32 = 256 MB scratch.
static __device__ float g_pair[8192UL * 8192UL];
static __device__ float g_wgt[1024 * 128];   // Wgt[k][o] = gamma[k]*W[o][k] (transposed)
static __device__ float g_sgw[128];          // sum_k gamma[k]*W[o][k]
static __device__ float g_sbw[128];          // sum_k beta[k]*W[o][k]
static __device__ float g_mu[256 * 256];
static __device__ float g_rstd[256 * 256];

// ---------- packed fp32x2 helpers (Blackwell dual-rate fp32 path) ----------
__device__ __forceinline__ void fma_f32x2(unsigned long long& d,
                                          unsigned long long a,
                                          unsigned long long b) {
    asm("fma.rn.f32x2 %0, %1, %2, %0;" : "+l"(d) : "l"(a), "l"(b));
}
__device__ __forceinline__ unsigned long long pack2(float x, float y) {
    unsigned long long r;
    asm("mov.b64 %0, {%1, %2};" : "=l"(r) : "f"(x), "f"(y));
    return r;
}
__device__ __forceinline__ unsigned long long bcast2(float x) {
    unsigned long long r;
    asm("mov.b64 %0, {%1, %1};" : "=l"(r) : "f"(x));
    return r;
}
__device__ __forceinline__ float2 unpack2(unsigned long long v) {
    float2 f;
    asm("mov.b64 {%0, %1}, %2;" : "=f"(f.x), "=f"(f.y) : "l"(v));
    return f;
}

// ---------- K0a: Wgt[k][o] = gamma[k] * W[o][k] ----------
__global__ void k0_prep(const float* __restrict__ W, const float* __restrict__ gamma) {
    int idx = blockIdx.x * 256 + threadIdx.x;  // 0..131071
    int k = idx >> 7;
    int o = idx & 127;
    g_wgt[idx] = gamma[k] * W[o * 1024 + k];
}

// ---------- K0b: Sgw[o], Sbw[o] ----------
__global__ void k0_sums(const float* __restrict__ W, const float* __restrict__ gamma,
                        const float* __restrict__ beta) {
    int o = threadIdx.x;  // 128 threads
    float sg = 0.f, sb = 0.f;
    for (int k = 0; k < 1024; ++k) {
        float w = W[o * 1024 + k];
        sg += gamma[k] * w;
        sb += beta[k] * w;
    }
    g_sgw[o] = sg;
    g_sbw[o] = sb;
}

// ---------- K1: pair = A^T * B  (TN GEMM, M=N=8192, K=128) ----------
// A = x_down viewed as [k=128][m=8192], B = x_down_w likewise (native layout).
// CTA tile 128x128, K streamed in 4 chunks of 32. 256 threads, 8x8 micro-tile
// as 8 rows x 4 f32x2 column-pairs. Split-half fragment mapping (tx*4 / 64+tx*4)
// keeps all shared loads conflict-free.
__global__ __launch_bounds__(256, 2) void k1_gemm1(const float* __restrict__ A,
                                                   const float* __restrict__ B) {
    __shared__ __align__(16) float As[32 * 128];
    __shared__ __align__(16) float Bs[32 * 128];
    const int p0 = blockIdx.y * 128;
    const int q0 = blockIdx.x * 128;
    const int t = threadIdx.x;
    const int tx = t & 15;
    const int ty = t >> 4;

    unsigned long long acc[8][4];
#pragma unroll
    for (int r = 0; r < 8; ++r)
#pragma unroll
        for (int c = 0; c < 4; ++c) acc[r][c] = 0ULL;

    const float4* A4 = (const float4*)A;
    const float4* B4 = (const float4*)B;
    float4* As4 = (float4*)As;
    float4* Bs4 = (float4*)Bs;

    for (int kc = 0; kc < 4; ++kc) {
        __syncthreads();  // previous chunk fully consumed
#pragma unroll
        for (int it = 0; it < 4; ++it) {
            int idx = it * 256 + t;  // 0..1023 float4s
            int row = idx >> 5;      // 0..31 (k within chunk)
            int c = idx & 31;        // float4 column
            As4[row * 32 + c] = A4[(size_t)(kc * 32 + row) * 2048 + (p0 >> 2) + c];
            Bs4[row * 32 + c] = B4[(size_t)(kc * 32 + row) * 2048 + (q0 >> 2) + c];
        }
        __syncthreads();
#pragma unroll 8
        for (int k = 0; k < 32; ++k) {
            float4 a0 = As4[k * 32 + ty];       // rows ty*4..+3
            float4 a1 = As4[k * 32 + 16 + ty];  // rows 64+ty*4..+3
            float4 b0 = Bs4[k * 32 + tx];       // cols tx*4..+3
            float4 b1 = Bs4[k * 32 + 16 + tx];  // cols 64+tx*4..+3
            unsigned long long bv0 = pack2(b0.x, b0.y);
            unsigned long long bv1 = pack2(b0.z, b0.w);
            unsigned long long bv2 = pack2(b1.x, b1.y);
            unsigned long long bv3 = pack2(b1.z, b1.w);
            float av[8] = {a0.x, a0.y, a0.z, a0.w, a1.x, a1.y, a1.z, a1.w};
#pragma unroll
            for (int r = 0; r < 8; ++r) {
                unsigned long long a2 = bcast2(av[r]);
                fma_f32x2(acc[r][0], a2, bv0);
                fma_f32x2(acc[r][1], a2, bv1);
                fma_f32x2(acc[r][2], a2, bv2);
                fma_f32x2(acc[r][3], a2, bv3);
            }
        }
    }

    float4* gp4 = (float4*)g_pair;
#pragma unroll
    for (int r = 0; r < 8; ++r) {
        int pr = p0 + ((r < 4) ? (ty * 4 + r) : (64 + ty * 4 + r - 4));
        float2 c0 = unpack2(acc[r][0]);
        float2 c1 = unpack2(acc[r][1]);
        float2 c2 = unpack2(acc[r][2]);
        float2 c3 = unpack2(acc[r][3]);
        gp4[(size_t)pr * 2048 + (q0 >> 2) + tx] = make_float4(c0.x, c0.y, c1.x, c1.y);
        gp4[(size_t)pr * 2048 + (q0 >> 2) + 16 + tx] = make_float4(c2.x, c2.y, c3.x, c3.y);
    }
}

// ---------- K2: per-(i,l) LayerNorm stats over the 32x32 pair block ----------
__global__ void k2_stats() {
    int cell = blockIdx.x * 8 + (threadIdx.x >> 5);  // 8 warps/CTA, one cell each
    int lane = threadIdx.x & 31;
    int i = cell >> 8;
    int l = cell & 255;
    const float* base = g_pair + (size_t)(i * 32) * 8192 + l * 32;
    float s = 0.f, ss = 0.f;
#pragma unroll
    for (int j = 0; j < 32; ++j) {
        float v = base[(size_t)j * 8192 + lane];
        s += v;
        ss += v * v;
    }
#pragma unroll
    for (int o = 16; o; o >>= 1) {
        s += __shfl_xor_sync(0xFFFFFFFFu, s, o);
        ss += __shfl_xor_sync(0xFFFFFFFFu, ss, o);
    }
    if (lane == 0) {
        float mu = s * (1.f / 1024.f);
        float var = ss * (1.f / 1024.f) - mu * mu;
        g_mu[cell] = mu;
        g_rstd[cell] = rsqrtf(var + LN_EPS);
    }
}

// ---------- K3: out[(i,l),o] = rstd*(pair@Wgt - mu*Sgw) + Sbw + b ----------
// CTA: fixed i, 128 l's, all 128 o's; K=1024 streamed as 32 chunks (one j each).
// Pair chunk transposed into Ps[m][tl] with 129-float stride (conflict-free
// scalar stores/broadcast loads); Wgt chunk [m][o] copied straight.
__global__ __launch_bounds__(256, 2) void k3_gemm2(float* __restrict__ out,
                                                   const float* __restrict__ bias) {
    __shared__ float Ps[32][129];
    __shared__ __align__(16) float Ws[32 * 128];
    const int i = blockIdx.y;
    const int l0 = blockIdx.x * 128;
    const int t = threadIdx.x;
    const int tx = t & 15;
    const int ty = t >> 4;

    unsigned long long acc[8][4];
#pragma unroll
    for (int r = 0; r < 8; ++r)
#pragma unroll
        for (int c = 0; c < 4; ++c) acc[r][c] = 0ULL;

    float4* Ws4 = (float4*)Ws;
    for (int j = 0; j < 32; ++j) {
        __syncthreads();
        const float4* src = (const float4*)(g_pair + (size_t)(i * 32 + j) * 8192 + l0 * 32);
#pragma unroll
        for (int it = 0; it < 4; ++it) {
            int idx = it * 256 + t;  // 0..1023 float4s (128 l x 8 float4)
            float4 v = src[idx];
            int tl = idx >> 3;
            int m4 = idx & 7;
            Ps[m4 * 4 + 0][tl] = v.x;
            Ps[m4 * 4 + 1][tl] = v.y;
            Ps[m4 * 4 + 2][tl] = v.z;
            Ps[m4 * 4 + 3][tl] = v.w;
        }
        const float4* wsrc = (const float4*)(g_wgt + j * 32 * 128);
#pragma unroll
        for (int it = 0; it < 4; ++it) {
            int idx = it * 256 + t;
            Ws4[idx] = wsrc[idx];
        }
        __syncthreads();
#pragma unroll 4
        for (int m = 0; m < 32; ++m) {
            float4 b0 = ((float4*)(Ws + m * 128))[tx];
            float4 b1 = ((float4*)(Ws + m * 128 + 64))[tx];
            unsigned long long bv0 = pack2(b0.x, b0.y);
            unsigned long long bv1 = pack2(b0.z, b0.w);
            unsigned long long bv2 = pack2(b1.x, b1.y);
            unsigned long long bv3 = pack2(b1.z, b1.w);
            float av[8];
#pragma unroll
            for (int r = 0; r < 4; ++r) {
                av[r] = Ps[m][ty * 4 + r];
                av[4 + r] = Ps[m][64 + ty * 4 + r];
            }
#pragma unroll
            for (int r = 0; r < 8; ++r) {
                unsigned long long a2 = bcast2(av[r]);
                fma_f32x2(acc[r][0], a2, bv0);
                fma_f32x2(acc[r][1], a2, bv1);
                fma_f32x2(acc[r][2], a2, bv2);
                fma_f32x2(acc[r][3], a2, bv3);
            }
        }
    }

    // Epilogue: fold LayerNorm affine + bias.
    float4 sg0 = ((const float4*)g_sgw)[tx], sg1 = ((const float4*)g_sgw)[16 + tx];
    float4 sb0 = ((const float4*)g_sbw)[tx], sb1 = ((const float4*)g_sbw)[16 + tx];
    float4 bb0 = ((const float4*)bias)[tx], bb1 = ((const float4*)bias)[16 + tx];
    float sgv[8] = {sg0.x, sg0.y, sg0.z, sg0.w, sg1.x, sg1.y, sg1.z, sg1.w};
    float sbv[8] = {sb0.x, sb0.y, sb0.z, sb0.w, sb1.x, sb1.y, sb1.z, sb1.w};
    float bbv[8] = {bb0.x, bb0.y, bb0.z, bb0.w, bb1.x, bb1.y, bb1.z, bb1.w};

#pragma unroll
    for (int r = 0; r < 8; ++r) {
        int l = l0 + ((r < 4) ? (ty * 4 + r) : (64 + ty * 4 + r - 4));
        int cell = i * 256 + l;
        float mu = g_mu[cell];
        float rs = g_rstd[cell];
        float2 c0 = unpack2(acc[r][0]);
        float2 c1 = unpack2(acc[r][1]);
        float2 c2 = unpack2(acc[r][2]);
        float2 c3 = unpack2(acc[r][3]);
        float v[8] = {c0.x, c0.y, c1.x, c1.y, c2.x, c2.y, c3.x, c3.y};
        float o8[8];
#pragma unroll
        for (int c = 0; c < 8; ++c) o8[c] = rs * (v[c] - mu * sgv[c]) + sbv[c] + bbv[c];
        float4* dst = (float4*)(out + (size_t)cell * 128);
        dst[tx] = make_float4(o8[0], o8[1], o8[2], o8[3]);
        dst[16 + tx] = make_float4(o8[4], o8[5], o8[6], o8[7]);
    }
}

extern "C" void kernel_launch(void* const* d_in, const int* in_sizes, int n_in,
                              void* d_out, int out_size) {
    const float* x_down = (const float*)d_in[0];
    const float* x_down_w = (const float*)d_in[1];
    const float* ln_gamma = (const float*)d_in[2];
    const float* ln_beta = (const float*)d_in[3];
    const float* W = (const float*)d_in[4];
    const float* b = (const float*)d_in[5];
    float* out = (float*)d_out;

    k0_prep<<<512, 256>>>(W, ln_gamma);
    k0_sums<<<1, 128>>>(W, ln_gamma, ln_beta);
    k1_gemm1<<<dim3(64, 64), 256>>>(x_down, x_down_w);
    k2_stats<<<8192, 256>>>();
    k3_gemm2<<<dim3(2, 256), 256>>>(out, b);
}

// round 4
// speedup vs baseline: 2.3612x; 2.3612x over previous
#include <cuda_runtime.h>
#include <cstdint>
#include <cstddef>

#define LN_EPS 1e-5f

// Shapes: N=128, L=256, P=32. pair2: [(i*256+l)][j*32+m] = [65536][1024]
static __device__ float g_at[8192UL * 128];     // x_down^T   [m][k], tf32-rounded
static __device__ float g_bt[8192UL * 128];     // x_down_w^T [m][k], tf32-rounded
static __device__ float g_pair2[65536UL * 1024UL];
static __device__ float g_wgt[128 * 1024];      // [o][k] = rn(gamma[k]*W[o][k])
static __device__ float g_sgw[128];
static __device__ float g_sbw[128];             // beta-proj + bias
static __device__ float g_mu[65536];
static __device__ float g_rstd[65536];

// ---------------- helpers ----------------
__device__ __forceinline__ uint32_t smem_u32(const void* p) {
    uint32_t a;
    asm("{ .reg .u64 t; cvta.to.shared.u64 t, %1; cvt.u32.u64 %0, t; }" : "=r"(a) : "l"(p));
    return a;
}
__device__ __forceinline__ float rnd_tf32(float x) {
    uint32_t u = __float_as_uint(x);
    u = (u + 0xFFFu + ((u >> 13) & 1u)) & 0xFFFFE000u;
    return __uint_as_float(u);
}
__device__ __forceinline__ void cpa16(uint32_t s, const float* g) {
    asm volatile("cp.async.cg.shared.global [%0], [%1], 16;" :: "r"(s), "l"(g));
}
__device__ __forceinline__ void cpa_commit() {
    asm volatile("cp.async.commit_group;");
}
template <int N>
__device__ __forceinline__ void cpa_wait() {
    asm volatile("cp.async.wait_group %0;" :: "n"(N));
}
__device__ __forceinline__ void mma_tf32(float* d, const uint32_t* a, const uint32_t* b) {
    asm volatile(
        "mma.sync.aligned.m16n8k8.row.col.f32.tf32.tf32.f32 "
        "{%0,%1,%2,%3}, {%4,%5,%6,%7}, {%8,%9}, {%0,%1,%2,%3};"
        : "+f"(d[0]), "+f"(d[1]), "+f"(d[2]), "+f"(d[3])
        : "r"(a[0]), "r"(a[1]), "r"(a[2]), "r"(a[3]), "r"(b[0]), "r"(b[1]));
}

// ---------- K0a: g_wgt[o][k] = rn(gamma[k]*W[o][k]) ----------
__global__ void k0_prep(const float* __restrict__ W, const float* __restrict__ gamma) {
    int idx = blockIdx.x * 256 + threadIdx.x;  // [o][k] native
    g_wgt[idx] = rnd_tf32(W[idx] * gamma[idx & 1023]);
}

// ---------- K0b: Sgw[o], Sbw[o]+bias[o] ----------
__global__ void k0_sums(const float* __restrict__ W, const float* __restrict__ gamma,
                        const float* __restrict__ beta, const float* __restrict__ bias) {
    int o = threadIdx.x;
    float sg = 0.f, sb = 0.f;
    for (int k = 0; k < 1024; ++k) {
        float w = W[o * 1024 + k];
        sg += gamma[k] * w;
        sb += beta[k] * w;
    }
    g_sgw[o] = sg;
    g_sbw[o] = sb + bias[o];
}

// ---------- KT: transpose [k=128][m=8192] -> [m][k], tf32 round ----------
__global__ void kT(const float* __restrict__ A, const float* __restrict__ B) {
    __shared__ float s[32][33];
    const float* src = blockIdx.z ? B : A;
    float* dst = blockIdx.z ? g_bt : g_at;
    const int m0 = blockIdx.x * 32, k0 = blockIdx.y * 32;
    const int tx = threadIdx.x & 31, ty = threadIdx.x >> 5;
#pragma unroll
    for (int i = 0; i < 4; ++i)
        s[ty + i * 8][tx] = src[(size_t)(k0 + ty + i * 8) * 8192 + m0 + tx];
    __syncthreads();
#pragma unroll
    for (int i = 0; i < 4; ++i)
        dst[(size_t)(m0 + ty + i * 8) * 128 + k0 + tx] = rnd_tf32(s[tx][ty + i * 8]);
}

// Common tile geometry: CTA 128x128, 8 warps (2 M x 4 N), warp tile 64x32,
// k-chunks of 32, smem row stride 36 floats (fragment LDS bank == lane id).
#define TILE_F 4608          // 128*36 floats per operand tile
#define BUF_F 9216           // A+B per buffer
#define SMEM_BYTES (2 * BUF_F * 4)

// ---------- K1: pair = At*Bt^T + fused LN stats + pair2 store ----------
__global__ __launch_bounds__(256) void k1_gemm1() {
    extern __shared__ float sm[];
    const int t = threadIdx.x, w = t >> 5, ln = t & 31;
    const int wy = w >> 2, wx = w & 3;
    const int p0 = blockIdx.y * 128, q0 = blockIdx.x * 128;
    const uint32_t sbase = smem_u32(sm);

    float acc[4][4][4];
#pragma unroll
    for (int mt = 0; mt < 4; ++mt)
#pragma unroll
        for (int nt = 0; nt < 4; ++nt)
#pragma unroll
            for (int r = 0; r < 4; ++r) acc[mt][nt][r] = 0.f;

    auto load_chunk = [&](int kc, int buf) {
        const float* gA = g_at + (size_t)p0 * 128 + kc * 32;
        const float* gB = g_bt + (size_t)q0 * 128 + kc * 32;
        uint32_t sA = sbase + buf * (BUF_F * 4);
        uint32_t sB = sA + TILE_F * 4;
#pragma unroll
        for (int it = 0; it < 4; ++it) {
            int idx = it * 256 + t;
            int row = idx >> 3, k4 = idx & 7;
            cpa16(sA + (row * 36 + k4 * 4) * 4, gA + (size_t)row * 128 + k4 * 4);
            cpa16(sB + (row * 36 + k4 * 4) * 4, gB + (size_t)row * 128 + k4 * 4);
        }
        cpa_commit();
    };

    load_chunk(0, 0);
    for (int kc = 0; kc < 4; ++kc) {
        if (kc < 3) { load_chunk(kc + 1, (kc + 1) & 1); cpa_wait<1>(); }
        else cpa_wait<0>();
        __syncthreads();
        const float* As = sm + (kc & 1) * BUF_F;
        const float* Bs = As + TILE_F;
#pragma unroll
        for (int ks = 0; ks < 4; ++ks) {
            const int kk = ks * 8 + (ln & 3);
            uint32_t a[4][4], b[4][2];
            const int rA = wy * 64 + (ln >> 2);
#pragma unroll
            for (int mt = 0; mt < 4; ++mt) {
                int m = rA + 16 * mt;
                a[mt][0] = __float_as_uint(As[m * 36 + kk]);
                a[mt][1] = __float_as_uint(As[(m + 8) * 36 + kk]);
                a[mt][2] = __float_as_uint(As[m * 36 + kk + 4]);
                a[mt][3] = __float_as_uint(As[(m + 8) * 36 + kk + 4]);
            }
            const int rB = wx * 32 + (ln >> 2);
#pragma unroll
            for (int nt = 0; nt < 4; ++nt) {
                int n = rB + 8 * nt;
                b[nt][0] = __float_as_uint(Bs[n * 36 + kk]);
                b[nt][1] = __float_as_uint(Bs[n * 36 + kk + 4]);
            }
#pragma unroll
            for (int mt = 0; mt < 4; ++mt)
#pragma unroll
                for (int nt = 0; nt < 4; ++nt) mma_tf32(acc[mt][nt], a[mt], b[nt]);
        }
        __syncthreads();
    }

    // Fused LN stats: warp tile = 2 cells (mt 0,1 -> cell0; mt 2,3 -> cell1)
    float s2[2] = {0.f, 0.f}, q2[2] = {0.f, 0.f};
#pragma unroll
    for (int mt = 0; mt < 4; ++mt)
#pragma unroll
        for (int nt = 0; nt < 4; ++nt)
#pragma unroll
            for (int r = 0; r < 4; ++r) {
                float v = acc[mt][nt][r];
                s2[mt >> 1] += v;
                q2[mt >> 1] += v * v;
            }
#pragma unroll
    for (int o = 16; o; o >>= 1) {
        s2[0] += __shfl_xor_sync(0xFFFFFFFFu, s2[0], o);
        q2[0] += __shfl_xor_sync(0xFFFFFFFFu, q2[0], o);
        s2[1] += __shfl_xor_sync(0xFFFFFFFFu, s2[1], o);
        q2[1] += __shfl_xor_sync(0xFFFFFFFFu, q2[1], o);
    }
    const int iA = blockIdx.y * 4 + wy * 2;    // i of cell0 (cell1 = iA+1)
    const int lA = blockIdx.x * 4 + wx;        // l
    if (ln == 0) {
#pragma unroll
        for (int c = 0; c < 2; ++c) {
            int cell = (iA + c) * 256 + lA;
            float mu = s2[c] * (1.f / 1024.f);
            g_mu[cell] = mu;
            g_rstd[cell] = rsqrtf(q2[c] * (1.f / 1024.f) - mu * mu + LN_EPS);
        }
    }

    // pair2[(i*256+l)][j*32+m]  (j = p%32, m = q%32), tf32-rounded, float2 stores
#pragma unroll
    for (int mt = 0; mt < 4; ++mt) {
        const size_t row = (size_t)((iA + (mt >> 1)) * 256 + lA) * 1024;
        const int j1 = 16 * (mt & 1) + (ln >> 2);
#pragma unroll
        for (int nt = 0; nt < 4; ++nt) {
            const int qm = 8 * nt + 2 * (ln & 3);
            float2 v01 = make_float2(rnd_tf32(acc[mt][nt][0]), rnd_tf32(acc[mt][nt][1]));
            float2 v23 = make_float2(rnd_tf32(acc[mt][nt][2]), rnd_tf32(acc[mt][nt][3]));
            *(float2*)(g_pair2 + row + j1 * 32 + qm) = v01;
            *(float2*)(g_pair2 + row + (j1 + 8) * 32 + qm) = v23;
        }
    }
}

// ---------- K3: out = rstd*(pair2 @ Wgt^T - mu*Sgw) + Sbw ----------
__global__ __launch_bounds__(256) void k3_gemm2(float* __restrict__ out) {
    extern __shared__ float sm[];
    const int t = threadIdx.x, w = t >> 5, ln = t & 31;
    const int wy = w >> 2, wx = w & 3;
    const int m0 = blockIdx.x * 128;
    const uint32_t sbase = smem_u32(sm);

    float acc[4][4][4];
#pragma unroll
    for (int mt = 0; mt < 4; ++mt)
#pragma unroll
        for (int nt = 0; nt < 4; ++nt)
#pragma unroll
            for (int r = 0; r < 4; ++r) acc[mt][nt][r] = 0.f;

    auto load_chunk = [&](int kc, int buf) {
        const float* gA = g_pair2 + (size_t)m0 * 1024 + kc * 32;
        const float* gB = g_wgt + kc * 32;
        uint32_t sA = sbase + buf * (BUF_F * 4);
        uint32_t sB = sA + TILE_F * 4;
#pragma unroll
        for (int it = 0; it < 4; ++it) {
            int idx = it * 256 + t;
            int row = idx >> 3, k4 = idx & 7;
            cpa16(sA + (row * 36 + k4 * 4) * 4, gA + (size_t)row * 1024 + k4 * 4);
            cpa16(sB + (row * 36 + k4 * 4) * 4, gB + (size_t)row * 1024 + k4 * 4);
        }
        cpa_commit();
    };

    load_chunk(0, 0);
    for (int kc = 0; kc < 32; ++kc) {
        if (kc < 31) { load_chunk(kc + 1, (kc + 1) & 1); cpa_wait<1>(); }
        else cpa_wait<0>();
        __syncthreads();
        const float* As = sm + (kc & 1) * BUF_F;
        const float* Bs = As + TILE_F;
#pragma unroll
        for (int ks = 0; ks < 4; ++ks) {
            const int kk = ks * 8 + (ln & 3);
            uint32_t a[4][4], b[4][2];
            const int rA = wy * 64 + (ln >> 2);
#pragma unroll
            for (int mt = 0; mt < 4; ++mt) {
                int m = rA + 16 * mt;
                a[mt][0] = __float_as_uint(As[m * 36 + kk]);
                a[mt][1] = __float_as_uint(As[(m + 8) * 36 + kk]);
                a[mt][2] = __float_as_uint(As[m * 36 + kk + 4]);
                a[mt][3] = __float_as_uint(As[(m + 8) * 36 + kk + 4]);
            }
            const int rB = wx * 32 + (ln >> 2);
#pragma unroll
            for (int nt = 0; nt < 4; ++nt) {
                int n = rB + 8 * nt;
                b[nt][0] = __float_as_uint(Bs[n * 36 + kk]);
                b[nt][1] = __float_as_uint(Bs[n * 36 + kk + 4]);
            }
#pragma unroll
            for (int mt = 0; mt < 4; ++mt)
#pragma unroll
                for (int nt = 0; nt < 4; ++nt) mma_tf32(acc[mt][nt], a[mt], b[nt]);
        }
        __syncthreads();
    }

    // Epilogue: LN affine + bias, direct stores
#pragma unroll
    for (int mt = 0; mt < 4; ++mt) {
        const int r1 = m0 + wy * 64 + 16 * mt + (ln >> 2);
        const int r2 = r1 + 8;
        const float mu1 = g_mu[r1], rs1 = g_rstd[r1];
        const float mu2 = g_mu[r2], rs2 = g_rstd[r2];
#pragma unroll
        for (int nt = 0; nt < 4; ++nt) {
            const int o1 = wx * 32 + 8 * nt + 2 * (ln & 3);
            const float2 sg = *(const float2*)(g_sgw + o1);
            const float2 sb = *(const float2*)(g_sbw + o1);
            float2 v1, v2;
            v1.x = rs1 * (acc[mt][nt][0] - mu1 * sg.x) + sb.x;
            v1.y = rs1 * (acc[mt][nt][1] - mu1 * sg.y) + sb.y;
            v2.x = rs2 * (acc[mt][nt][2] - mu2 * sg.x) + sb.x;
            v2.y = rs2 * (acc[mt][nt][3] - mu2 * sg.y) + sb.y;
            *(float2*)(out + (size_t)r1 * 128 + o1) = v1;
            *(float2*)(out + (size_t)r2 * 128 + o1) = v2;
        }
    }
}

extern "C" void kernel_launch(void* const* d_in, const int* in_sizes, int n_in,
                              void* d_out, int out_size) {
    const float* x_down = (const float*)d_in[0];
    const float* x_down_w = (const float*)d_in[1];
    const float* ln_gamma = (const float*)d_in[2];
    const float* ln_beta = (const float*)d_in[3];
    const float* W = (const float*)d_in[4];
    const float* b = (const float*)d_in[5];
    float* out = (float*)d_out;

    cudaFuncSetAttribute(k1_gemm1, cudaFuncAttributeMaxDynamicSharedMemorySize, SMEM_BYTES);
    cudaFuncSetAttribute(k3_gemm2, cudaFuncAttributeMaxDynamicSharedMemorySize, SMEM_BYTES);

    k0_prep<<<512, 256>>>(W, ln_gamma);
    k0_sums<<<1, 128>>>(W, ln_gamma, ln_beta, b);
    kT<<<dim3(256, 4, 2), 256>>>(x_down, x_down_w);
    k1_gemm1<<<dim3(64, 64), 256, SMEM_BYTES>>>();
    k3_gemm2<<<512, 256, SMEM_BYTES>>>(out);
}

// round 6
// speedup vs baseline: 2.5171x; 1.0660x over previous
#include <cuda_runtime.h>
#include <cstdint>
#include <cstddef>

#define LN_EPS 1e-5f

// Shapes: N=128, L=256, P=32. pair2: [(i*256+l)][j*32+m] = [65536][1024]
static __device__ float g_at[8192UL * 128];     // x_down^T   [m][k], tf32-rounded
static __device__ float g_bt[8192UL * 128];     // x_down_w^T [m][k], tf32-rounded
static __device__ float g_pair2[65536UL * 1024UL];
static __device__ float g_wgt[128 * 1024];      // [o][k] = rn(gamma[k]*W[o][k])
static __device__ float g_sgw[128];
static __device__ float g_sbw[128];             // beta-proj + bias
static __device__ float g_mu[65536];
static __device__ float g_rstd[65536];

// ---------------- helpers ----------------
__device__ __forceinline__ uint32_t smem_u32(const void* p) {
    uint32_t a;
    asm("{ .reg .u64 t; cvta.to.shared.u64 t, %1; cvt.u32.u64 %0, t; }" : "=r"(a) : "l"(p));
    return a;
}
__device__ __forceinline__ float rnd_tf32(float x) {
    uint32_t u = __float_as_uint(x);
    u = (u + 0xFFFu + ((u >> 13) & 1u)) & 0xFFFFE000u;
    return __uint_as_float(u);
}
__device__ __forceinline__ void cpa16(uint32_t s, const float* g) {
    asm volatile("cp.async.cg.shared.global [%0], [%1], 16;" :: "r"(s), "l"(g));
}
__device__ __forceinline__ void cpa_commit() {
    asm volatile("cp.async.commit_group;");
}
template <int N>
__device__ __forceinline__ void cpa_wait() {
    asm volatile("cp.async.wait_group %0;" :: "n"(N));
}
__device__ __forceinline__ void mma_tf32(float* d, const uint32_t* a, const uint32_t* b) {
    asm volatile(
        "mma.sync.aligned.m16n8k8.row.col.f32.tf32.tf32.f32 "
        "{%0,%1,%2,%3}, {%4,%5,%6,%7}, {%8,%9}, {%0,%1,%2,%3};"
        : "+f"(d[0]), "+f"(d[1]), "+f"(d[2]), "+f"(d[3])
        : "r"(a[0]), "r"(a[1]), "r"(a[2]), "r"(a[3]), "r"(b[0]), "r"(b[1]));
}

// ---------- K0a ----------
__global__ void k0_prep(const float* __restrict__ W, const float* __restrict__ gamma) {
    int idx = blockIdx.x * 256 + threadIdx.x;
    g_wgt[idx] = rnd_tf32(W[idx] * gamma[idx & 1023]);
}

// ---------- K0b ----------
__global__ void k0_sums(const float* __restrict__ W, const float* __restrict__ gamma,
                        const float* __restrict__ beta, const float* __restrict__ bias) {
    int o = threadIdx.x;
    float sg = 0.f, sb = 0.f;
    for (int k = 0; k < 1024; ++k) {
        float w = W[o * 1024 + k];
        sg += gamma[k] * w;
        sb += beta[k] * w;
    }
    g_sgw[o] = sg;
    g_sbw[o] = sb + bias[o];
}

// ---------- KT: transpose [k=128][m=8192] -> [m][k], tf32 round ----------
__global__ void kT(const float* __restrict__ A, const float* __restrict__ B) {
    __shared__ float s[32][33];
    const float* src = blockIdx.z ? B : A;
    float* dst = blockIdx.z ? g_bt : g_at;
    const int m0 = blockIdx.x * 32, k0 = blockIdx.y * 32;
    const int tx = threadIdx.x & 31, ty = threadIdx.x >> 5;
#pragma unroll
    for (int i = 0; i < 4; ++i)
        s[ty + i * 8][tx] = src[(size_t)(k0 + ty + i * 8) * 8192 + m0 + tx];
    __syncthreads();
#pragma unroll
    for (int i = 0; i < 4; ++i)
        dst[(size_t)(m0 + ty + i * 8) * 128 + k0 + tx] = rnd_tf32(s[tx][ty + i * 8]);
}

// Tile geometry: CTA 128x128, 8 warps (2 M x 4 N), warp tile 64x32, k-chunks 32.
// Smem row stride 40 floats (20 f2 == 4 mod 16 -> LDS.64 conflict-free).
// Logical-k permutation: phys f2 (2c,2c+1) feeds logical lanes (c, c+4); identical
// for A and B, so the reduction is unchanged and every fragment pair is one LDS.64.
#define FSTR 40
#define TILE_F (128 * FSTR)
#define BUF_F (2 * TILE_F)
#define SMEM_BYTES (2 * BUF_F * 4)

// Fragment load for one ks step (shared by both GEMMs).
__device__ __forceinline__ void load_frags(const float* As, const float* Bs,
                                           int ks, int ln, int wy, int wx,
                                           uint32_t a[4][4], uint32_t b[4][2]) {
    const float2* As2 = (const float2*)As;
    const float2* Bs2 = (const float2*)Bs;
    const int cc = ks * 4 + (ln & 3);
    const int rA = wy * 64 + (ln >> 2);
#pragma unroll
    for (int mt = 0; mt < 4; ++mt) {
        int m = rA + 16 * mt;
        float2 lo = As2[m * (FSTR / 2) + cc];
        float2 hi = As2[(m + 8) * (FSTR / 2) + cc];
        a[mt][0] = __float_as_uint(lo.x);
        a[mt][1] = __float_as_uint(hi.x);
        a[mt][2] = __float_as_uint(lo.y);
        a[mt][3] = __float_as_uint(hi.y);
    }
    const int rB = wx * 32 + (ln >> 2);
#pragma unroll
    for (int nt = 0; nt < 4; ++nt) {
        float2 v = Bs2[(rB + 8 * nt) * (FSTR / 2) + cc];
        b[nt][0] = __float_as_uint(v.x);
        b[nt][1] = __float_as_uint(v.y);
    }
}

// ---------- K1: pair = At*Bt^T + fused LN stats + pair2 store ----------
__global__ __launch_bounds__(256, 2) void k1_gemm1() {
    extern __shared__ float sm[];
    const int t = threadIdx.x, w = t >> 5, ln = t & 31;
    const int wy = w >> 2, wx = w & 3;
    const int p0 = blockIdx.y * 128, q0 = blockIdx.x * 128;
    const uint32_t sbase = smem_u32(sm);

    float acc[4][4][4];
#pragma unroll
    for (int mt = 0; mt < 4; ++mt)
#pragma unroll
        for (int nt = 0; nt < 4; ++nt)
#pragma unroll
            for (int r = 0; r < 4; ++r) acc[mt][nt][r] = 0.f;

    auto load_chunk = [&](int kc, int buf) {
        const float* gA = g_at + (size_t)p0 * 128 + kc * 32;
        const float* gB = g_bt + (size_t)q0 * 128 + kc * 32;
        uint32_t sA = sbase + buf * (BUF_F * 4);
        uint32_t sB = sA + TILE_F * 4;
#pragma unroll
        for (int it = 0; it < 4; ++it) {
            int idx = it * 256 + t;
            int row = idx >> 3, k4 = idx & 7;
            cpa16(sA + (row * FSTR + k4 * 4) * 4, gA + (size_t)row * 128 + k4 * 4);
            cpa16(sB + (row * FSTR + k4 * 4) * 4, gB + (size_t)row * 128 + k4 * 4);
        }
        cpa_commit();
    };

    load_chunk(0, 0);
    for (int kc = 0; kc < 4; ++kc) {
        if (kc < 3) { load_chunk(kc + 1, (kc + 1) & 1); cpa_wait<1>(); }
        else cpa_wait<0>();
        __syncthreads();
        const float* As = sm + (kc & 1) * BUF_F;
        const float* Bs = As + TILE_F;
#pragma unroll
        for (int ks = 0; ks < 4; ++ks) {
            uint32_t a[4][4], b[4][2];
            load_frags(As, Bs, ks, ln, wy, wx, a, b);
#pragma unroll
            for (int mt = 0; mt < 4; ++mt)
#pragma unroll
                for (int nt = 0; nt < 4; ++nt) mma_tf32(acc[mt][nt], a[mt], b[nt]);
        }
        __syncthreads();
    }

    // Fused LN stats: warp tile = 2 cells (mt 0,1 -> cell0; mt 2,3 -> cell1)
    float s2[2] = {0.f, 0.f}, q2[2] = {0.f, 0.f};
#pragma unroll
    for (int mt = 0; mt < 4; ++mt)
#pragma unroll
        for (int nt = 0; nt < 4; ++nt)
#pragma unroll
            for (int r = 0; r < 4; ++r) {
                float v = acc[mt][nt][r];
                s2[mt >> 1] += v;
                q2[mt >> 1] += v * v;
            }
#pragma unroll
    for (int o = 16; o; o >>= 1) {
        s2[0] += __shfl_xor_sync(0xFFFFFFFFu, s2[0], o);
        q2[0] += __shfl_xor_sync(0xFFFFFFFFu, q2[0], o);
        s2[1] += __shfl_xor_sync(0xFFFFFFFFu, s2[1], o);
        q2[1] += __shfl_xor_sync(0xFFFFFFFFu, q2[1], o);
    }
    const int iA = blockIdx.y * 4 + wy * 2;
    const int lA = blockIdx.x * 4 + wx;
    if (ln == 0) {
#pragma unroll
        for (int c = 0; c < 2; ++c) {
            int cell = (iA + c) * 256 + lA;
            float mu = s2[c] * (1.f / 1024.f);
            g_mu[cell] = mu;
            g_rstd[cell] = rsqrtf(q2[c] * (1.f / 1024.f) - mu * mu + LN_EPS);
        }
    }

    // pair2[(i*256+l)][j*32+m], tf32-rounded
#pragma unroll
    for (int mt = 0; mt < 4; ++mt) {
        const size_t row = (size_t)((iA + (mt >> 1)) * 256 + lA) * 1024;
        const int j1 = 16 * (mt & 1) + (ln >> 2);
#pragma unroll
        for (int nt = 0; nt < 4; ++nt) {
            const int qm = 8 * nt + 2 * (ln & 3);
            float2 v01 = make_float2(rnd_tf32(acc[mt][nt][0]), rnd_tf32(acc[mt][nt][1]));
            float2 v23 = make_float2(rnd_tf32(acc[mt][nt][2]), rnd_tf32(acc[mt][nt][3]));
            *(float2*)(g_pair2 + row + j1 * 32 + qm) = v01;
            *(float2*)(g_pair2 + row + (j1 + 8) * 32 + qm) = v23;
        }
    }
}

// ---------- K3: out = rstd*(pair2 @ Wgt^T - mu*Sgw) + Sbw ----------
__global__ __launch_bounds__(256, 2) void k3_gemm2(float* __restrict__ out) {
    extern __shared__ float sm[];
    const int t = threadIdx.x, w = t >> 5, ln = t & 31;
    const int wy = w >> 2, wx = w & 3;
    const int m0 = blockIdx.x * 128;
    const uint32_t sbase = smem_u32(sm);

    float acc[4][4][4];
#pragma unroll
    for (int mt = 0; mt < 4; ++mt)
#pragma unroll
        for (int nt = 0; nt < 4; ++nt)
#pragma unroll
            for (int r = 0; r < 4; ++r) acc[mt][nt][r] = 0.f;

    auto load_chunk = [&](int kc, int buf) {
        const float* gA = g_pair2 + (size_t)m0 * 1024 + kc * 32;
        const float* gB = g_wgt + kc * 32;
        uint32_t sA = sbase + buf * (BUF_F * 4);
        uint32_t sB = sA + TILE_F * 4;
#pragma unroll
        for (int it = 0; it < 4; ++it) {
            int idx = it * 256 + t;
            int row = idx >> 3, k4 = idx & 7;
            cpa16(sA + (row * FSTR + k4 * 4) * 4, gA + (size_t)row * 1024 + k4 * 4);
            cpa16(sB + (row * FSTR + k4 * 4) * 4, gB + (size_t)row * 1024 + k4 * 4);
        }
        cpa_commit();
    };

    load_chunk(0, 0);
    for (int kc = 0; kc < 32; ++kc) {
        if (kc < 31) { load_chunk(kc + 1, (kc + 1) & 1); cpa_wait<1>(); }
        else cpa_wait<0>();
        __syncthreads();
        const float* As = sm + (kc & 1) * BUF_F;
        const float* Bs = As + TILE_F;
#pragma unroll
        for (int ks = 0; ks < 4; ++ks) {
            uint32_t a[4][4], b[4][2];
            load_frags(As, Bs, ks, ln, wy, wx, a, b);
#pragma unroll
            for (int mt = 0; mt < 4; ++mt)
#pragma unroll
                for (int nt = 0; nt < 4; ++nt) mma_tf32(acc[mt][nt], a[mt], b[nt]);
        }
        __syncthreads();
    }

    // Epilogue: LN affine + bias
#pragma unroll
    for (int mt = 0; mt < 4; ++mt) {
        const int r1 = m0 + wy * 64 + 16 * mt + (ln >> 2);
        const int r2 = r1 + 8;
        const float mu1 = g_mu[r1], rs1 = g_rstd[r1];
        const float mu2 = g_mu[r2], rs2 = g_rstd[r2];
#pragma unroll
        for (int nt = 0; nt < 4; ++nt) {
            const int o1 = wx * 32 + 8 * nt + 2 * (ln & 3);
            const float2 sg = *(const float2*)(g_sgw + o1);
            const float2 sb = *(const float2*)(g_sbw + o1);
            float2 v1, v2;
            v1.x = rs1 * (acc[mt][nt][0] - mu1 * sg.x) + sb.x;
            v1.y = rs1 * (acc[mt][nt][1] - mu1 * sg.y) + sb.y;
            v2.x = rs2 * (acc[mt][nt][2] - mu2 * sg.x) + sb.x;
            v2.y = rs2 * (acc[mt][nt][3] - mu2 * sg.y) + sb.y;
            *(float2*)(out + (size_t)r1 * 128 + o1) = v1;
            *(float2*)(out + (size_t)r2 * 128 + o1) = v2;
        }
    }
}

extern "C" void kernel_launch(void* const* d_in, const int* in_sizes, int n_in,
                              void* d_out, int out_size) {
    const float* x_down = (const float*)d_in[0];
    const float* x_down_w = (const float*)d_in[1];
    const float* ln_gamma = (const float*)d_in[2];
    const float* ln_beta = (const float*)d_in[3];
    const float* W = (const float*)d_in[4];
    const float* b = (const float*)d_in[5];
    float* out = (float*)d_out;

    cudaFuncSetAttribute(k1_gemm1, cudaFuncAttributeMaxDynamicSharedMemorySize, SMEM_BYTES);
    cudaFuncSetAttribute(k3_gemm2, cudaFuncAttributeMaxDynamicSharedMemorySize, SMEM_BYTES);

    k0_prep<<<512, 256>>>(W, ln_gamma);
    k0_sums<<<1, 128>>>(W, ln_gamma, ln_beta, b);
    kT<<<dim3(256, 4, 2), 256>>>(x_down, x_down_w);
    k1_gemm1<<<dim3(64, 64), 256, SMEM_BYTES>>>();
    k3_gemm2<<<512, 256, SMEM_BYTES>>>(out);
}

// round 7
// speedup vs baseline: 3.3515x; 1.3315x over previous
#include <cuda_runtime.h>
#include <cstdint>
#include <cstddef>

#define LN_EPS 1e-5f

// Shapes: N=128, L=256, P=32. pair2: [(i*256+l)][j*32+m] = [65536][1024]
static __device__ float g_at[8192UL * 128];     // x_down^T   [m][k], tf32-rounded
static __device__ float g_bt[8192UL * 128];     // x_down_w^T [m][k], tf32-rounded
static __device__ float g_pair2[65536UL * 1024UL];
static __device__ float g_wgt[128 * 1024];      // [o][k] = rn(gamma[k]*W[o][k])
static __device__ float g_sgw[128];
static __device__ float g_sbw[128];             // beta-proj + bias
static __device__ float g_mu[65536];
static __device__ float g_rstd[65536];

// ---------------- helpers ----------------
__device__ __forceinline__ uint32_t smem_u32(const void* p) {
    uint32_t a;
    asm("{ .reg .u64 t; cvta.to.shared.u64 t, %1; cvt.u32.u64 %0, t; }" : "=r"(a) : "l"(p));
    return a;
}
__device__ __forceinline__ float rnd_tf32(float x) {
    uint32_t u = __float_as_uint(x);
    u = (u + 0xFFFu + ((u >> 13) & 1u)) & 0xFFFFE000u;
    return __uint_as_float(u);
}
__device__ __forceinline__ void cpa16(uint32_t s, const float* g) {
    asm volatile("cp.async.cg.shared.global [%0], [%1], 16;" :: "r"(s), "l"(g));
}
__device__ __forceinline__ void cpa_commit() {
    asm volatile("cp.async.commit_group;");
}
template <int N>
__device__ __forceinline__ void cpa_wait() {
    asm volatile("cp.async.wait_group %0;" :: "n"(N));
}
__device__ __forceinline__ void mma_tf32(float* d, const uint32_t* a, const uint32_t* b) {
    asm volatile(
        "mma.sync.aligned.m16n8k8.row.col.f32.tf32.tf32.f32 "
        "{%0,%1,%2,%3}, {%4,%5,%6,%7}, {%8,%9}, {%0,%1,%2,%3};"
        : "+f"(d[0]), "+f"(d[1]), "+f"(d[2]), "+f"(d[3])
        : "r"(a[0]), "r"(a[1]), "r"(a[2]), "r"(a[3]), "r"(b[0]), "r"(b[1]));
}

// ---------- K0a ----------
__global__ void k0_prep(const float* __restrict__ W, const float* __restrict__ gamma) {
    int idx = blockIdx.x * 256 + threadIdx.x;
    g_wgt[idx] = rnd_tf32(W[idx] * gamma[idx & 1023]);
}

// ---------- K0b: one warp per o ----------
__global__ void k0_sums(const float* __restrict__ W, const float* __restrict__ gamma,
                        const float* __restrict__ beta, const float* __restrict__ bias) {
    int o = blockIdx.x, ln = threadIdx.x;
    float sg = 0.f, sb = 0.f;
    for (int k = ln; k < 1024; k += 32) {
        float w = W[o * 1024 + k];
        sg += gamma[k] * w;
        sb += beta[k] * w;
    }
#pragma unroll
    for (int s = 16; s; s >>= 1) {
        sg += __shfl_xor_sync(0xFFFFFFFFu, sg, s);
        sb += __shfl_xor_sync(0xFFFFFFFFu, sb, s);
    }
    if (ln == 0) {
        g_sgw[o] = sg;
        g_sbw[o] = sb + bias[o];
    }
}

// ---------- KT: transpose [k=128][m=8192] -> [m][k], tf32 round ----------
__global__ void kT(const float* __restrict__ A, const float* __restrict__ B) {
    __shared__ float s[32][33];
    const float* src = blockIdx.z ? B : A;
    float* dst = blockIdx.z ? g_bt : g_at;
    const int m0 = blockIdx.x * 32, k0 = blockIdx.y * 32;
    const int tx = threadIdx.x & 31, ty = threadIdx.x >> 5;
#pragma unroll
    for (int i = 0; i < 4; ++i)
        s[ty + i * 8][tx] = src[(size_t)(k0 + ty + i * 8) * 8192 + m0 + tx];
    __syncthreads();
#pragma unroll
    for (int i = 0; i < 4; ++i)
        dst[(size_t)(m0 + ty + i * 8) * 128 + k0 + tx] = rnd_tf32(s[tx][ty + i * 8]);
}

// Tile geometry: CTA 128x128, 4 warps (2 M x 2 N), warp tile 64x64, k-chunks 32.
// 128 threads/CTA -> 2 CTAs/SM at <=255 regs: ptxas free to pipeline frag loads.
// Smem row stride 40 floats (20 f2 == 4 mod 16 -> LDS.64 conflict-free).
// Logical-k permutation: phys f2 (2c,2c+1) feeds logical lanes (c, c+4).
#define FSTR 40
#define TILE_F (128 * FSTR)
#define BUF_F (2 * TILE_F)
#define SMEM_BYTES (2 * BUF_F * 4)

__device__ __forceinline__ void load_frags(const float* As, const float* Bs,
                                           int ks, int ln, int wy, int wx,
                                           uint32_t a[4][4], uint32_t b[8][2]) {
    const float2* As2 = (const float2*)As;
    const float2* Bs2 = (const float2*)Bs;
    const int cc = ks * 4 + (ln & 3);
    const int rA = wy * 64 + (ln >> 2);
#pragma unroll
    for (int mt = 0; mt < 4; ++mt) {
        int m = rA + 16 * mt;
        float2 lo = As2[m * (FSTR / 2) + cc];
        float2 hi = As2[(m + 8) * (FSTR / 2) + cc];
        a[mt][0] = __float_as_uint(lo.x);
        a[mt][1] = __float_as_uint(hi.x);
        a[mt][2] = __float_as_uint(lo.y);
        a[mt][3] = __float_as_uint(hi.y);
    }
    const int rB = wx * 64 + (ln >> 2);
#pragma unroll
    for (int nt = 0; nt < 8; ++nt) {
        float2 v = Bs2[(rB + 8 * nt) * (FSTR / 2) + cc];
        b[nt][0] = __float_as_uint(v.x);
        b[nt][1] = __float_as_uint(v.y);
    }
}

// ---------- K1: pair = At*Bt^T + fused LN stats + pair2 store ----------
__global__ __launch_bounds__(128) void k1_gemm1() {
    extern __shared__ float sm[];
    const int t = threadIdx.x, w = t >> 5, ln = t & 31;
    const int wy = w >> 1, wx = w & 1;
    const int p0 = blockIdx.y * 128, q0 = blockIdx.x * 128;
    const uint32_t sbase = smem_u32(sm);

    float acc[4][8][4];
#pragma unroll
    for (int mt = 0; mt < 4; ++mt)
#pragma unroll
        for (int nt = 0; nt < 8; ++nt)
#pragma unroll
            for (int r = 0; r < 4; ++r) acc[mt][nt][r] = 0.f;

    auto load_chunk = [&](int kc, int buf) {
        const float* gA = g_at + (size_t)p0 * 128 + kc * 32;
        const float* gB = g_bt + (size_t)q0 * 128 + kc * 32;
        uint32_t sA = sbase + buf * (BUF_F * 4);
        uint32_t sB = sA + TILE_F * 4;
#pragma unroll
        for (int it = 0; it < 8; ++it) {
            int idx = it * 128 + t;
            int row = idx >> 3, k4 = idx & 7;
            cpa16(sA + (row * FSTR + k4 * 4) * 4, gA + (size_t)row * 128 + k4 * 4);
            cpa16(sB + (row * FSTR + k4 * 4) * 4, gB + (size_t)row * 128 + k4 * 4);
        }
        cpa_commit();
    };

    load_chunk(0, 0);
    for (int kc = 0; kc < 4; ++kc) {
        if (kc < 3) { load_chunk(kc + 1, (kc + 1) & 1); cpa_wait<1>(); }
        else cpa_wait<0>();
        __syncthreads();
        const float* As = sm + (kc & 1) * BUF_F;
        const float* Bs = As + TILE_F;
#pragma unroll
        for (int ks = 0; ks < 4; ++ks) {
            uint32_t a[4][4], b[8][2];
            load_frags(As, Bs, ks, ln, wy, wx, a, b);
#pragma unroll
            for (int mt = 0; mt < 4; ++mt)
#pragma unroll
                for (int nt = 0; nt < 8; ++nt) mma_tf32(acc[mt][nt], a[mt], b[nt]);
        }
        __syncthreads();
    }

    // Fused LN stats: warp spans 2 i-cells (mt>>1) x 2 l-cells (nt>>2)
    float s2[2][2] = {{0.f, 0.f}, {0.f, 0.f}}, q2[2][2] = {{0.f, 0.f}, {0.f, 0.f}};
#pragma unroll
    for (int mt = 0; mt < 4; ++mt)
#pragma unroll
        for (int nt = 0; nt < 8; ++nt)
#pragma unroll
            for (int r = 0; r < 4; ++r) {
                float v = acc[mt][nt][r];
                s2[mt >> 1][nt >> 2] += v;
                q2[mt >> 1][nt >> 2] += v * v;
            }
#pragma unroll
    for (int o = 16; o; o >>= 1)
#pragma unroll
        for (int ci = 0; ci < 2; ++ci)
#pragma unroll
            for (int cl = 0; cl < 2; ++cl) {
                s2[ci][cl] += __shfl_xor_sync(0xFFFFFFFFu, s2[ci][cl], o);
                q2[ci][cl] += __shfl_xor_sync(0xFFFFFFFFu, q2[ci][cl], o);
            }
    const int iA = blockIdx.y * 4 + wy * 2;
    const int lA = blockIdx.x * 4 + wx * 2;
    if (ln == 0) {
#pragma unroll
        for (int ci = 0; ci < 2; ++ci)
#pragma unroll
            for (int cl = 0; cl < 2; ++cl) {
                int cell = (iA + ci) * 256 + lA + cl;
                float mu = s2[ci][cl] * (1.f / 1024.f);
                g_mu[cell] = mu;
                g_rstd[cell] = rsqrtf(q2[ci][cl] * (1.f / 1024.f) - mu * mu + LN_EPS);
            }
    }

    // pair2[(i*256+l)][j*32+m], tf32-rounded
#pragma unroll
    for (int mt = 0; mt < 4; ++mt) {
        const int j1 = 16 * (mt & 1) + (ln >> 2);
#pragma unroll
        for (int nt = 0; nt < 8; ++nt) {
            const size_t row = (size_t)((iA + (mt >> 1)) * 256 + lA + (nt >> 2)) * 1024;
            const int qm = 8 * (nt & 3) + 2 * (ln & 3);
            float2 v01 = make_float2(rnd_tf32(acc[mt][nt][0]), rnd_tf32(acc[mt][nt][1]));
            float2 v23 = make_float2(rnd_tf32(acc[mt][nt][2]), rnd_tf32(acc[mt][nt][3]));
            *(float2*)(g_pair2 + row + j1 * 32 + qm) = v01;
            *(float2*)(g_pair2 + row + (j1 + 8) * 32 + qm) = v23;
        }
    }
}

// ---------- K3: out = rstd*(pair2 @ Wgt^T - mu*Sgw) + Sbw ----------
__global__ __launch_bounds__(128) void k3_gemm2(float* __restrict__ out) {
    extern __shared__ float sm[];
    const int t = threadIdx.x, w = t >> 5, ln = t & 31;
    const int wy = w >> 1, wx = w & 1;
    const int m0 = blockIdx.x * 128;
    const uint32_t sbase = smem_u32(sm);

    float acc[4][8][4];
#pragma unroll
    for (int mt = 0; mt < 4; ++mt)
#pragma unroll
        for (int nt = 0; nt < 8; ++nt)
#pragma unroll
            for (int r = 0; r < 4; ++r) acc[mt][nt][r] = 0.f;

    auto load_chunk = [&](int kc, int buf) {
        const float* gA = g_pair2 + (size_t)m0 * 1024 + kc * 32;
        const float* gB = g_wgt + kc * 32;
        uint32_t sA = sbase + buf * (BUF_F * 4);
        uint32_t sB = sA + TILE_F * 4;
#pragma unroll
        for (int it = 0; it < 8; ++it) {
            int idx = it * 128 + t;
            int row = idx >> 3, k4 = idx & 7;
            cpa16(sA + (row * FSTR + k4 * 4) * 4, gA + (size_t)row * 1024 + k4 * 4);
            cpa16(sB + (row * FSTR + k4 * 4) * 4, gB + (size_t)row * 1024 + k4 * 4);
        }
        cpa_commit();
    };

    load_chunk(0, 0);
    for (int kc = 0; kc < 32; ++kc) {
        if (kc < 31) { load_chunk(kc + 1, (kc + 1) & 1); cpa_wait<1>(); }
        else cpa_wait<0>();
        __syncthreads();
        const float* As = sm + (kc & 1) * BUF_F;
        const float* Bs = As + TILE_F;
#pragma unroll
        for (int ks = 0; ks < 4; ++ks) {
            uint32_t a[4][4], b[8][2];
            load_frags(As, Bs, ks, ln, wy, wx, a, b);
#pragma unroll
            for (int mt = 0; mt < 4; ++mt)
#pragma unroll
                for (int nt = 0; nt < 8; ++nt) mma_tf32(acc[mt][nt], a[mt], b[nt]);
        }
        __syncthreads();
    }

    // Epilogue: LN affine + bias
#pragma unroll
    for (int mt = 0; mt < 4; ++mt) {
        const int r1 = m0 + wy * 64 + 16 * mt + (ln >> 2);
        const int r2 = r1 + 8;
        const float mu1 = g_mu[r1], rs1 = g_rstd[r1];
        const float mu2 = g_mu[r2], rs2 = g_rstd[r2];
#pragma unroll
        for (int nt = 0; nt < 8; ++nt) {
            const int o1 = wx * 64 + 8 * nt + 2 * (ln & 3);
            const float2 sg = *(const float2*)(g_sgw + o1);
            const float2 sb = *(const float2*)(g_sbw + o1);
            float2 v1, v2;
            v1.x = rs1 * (acc[mt][nt][0] - mu1 * sg.x) + sb.x;
            v1.y = rs1 * (acc[mt][nt][1] - mu1 * sg.y) + sb.y;
            v2.x = rs2 * (acc[mt][nt][2] - mu2 * sg.x) + sb.x;
            v2.y = rs2 * (acc[mt][nt][3] - mu2 * sg.y) + sb.y;
            *(float2*)(out + (size_t)r1 * 128 + o1) = v1;
            *(float2*)(out + (size_t)r2 * 128 + o1) = v2;
        }
    }
}

extern "C" void kernel_launch(void* const* d_in, const int* in_sizes, int n_in,
                              void* d_out, int out_size) {
    const float* x_down = (const float*)d_in[0];
    const float* x_down_w = (const float*)d_in[1];
    const float* ln_gamma = (const float*)d_in[2];
    const float* ln_beta = (const float*)d_in[3];
    const float* W = (const float*)d_in[4];
    const float* b = (const float*)d_in[5];
    float* out = (float*)d_out;

    cudaFuncSetAttribute(k1_gemm1, cudaFuncAttributeMaxDynamicSharedMemorySize, SMEM_BYTES);
    cudaFuncSetAttribute(k3_gemm2, cudaFuncAttributeMaxDynamicSharedMemorySize, SMEM_BYTES);

    k0_prep<<<512, 256>>>(W, ln_gamma);
    k0_sums<<<128, 32>>>(W, ln_gamma, ln_beta, b);
    kT<<<dim3(256, 4, 2), 256>>>(x_down, x_down_w);
    k1_gemm1<<<dim3(64, 64), 128, SMEM_BYTES>>>();
    k3_gemm2<<<512, 128, SMEM_BYTES>>>(out);
}